// round 16
// baseline (speedup 1.0000x reference)
#include <cuda_runtime.h>
#include <cstdint>
#include <cstddef>

// Problem constants (fixed-shape problem):
//   grad_last: (B=8, M=4096) float32
//   indices:   (M=4096,) int32, values in [0, N=2048)
//   out:       (8, 4096, 2048) float32  -> 256 MB
//
// out[b, i, j] = (j == indices[i]) ? grad_last[b, i] : 0
//
// FINAL ROOFLINE KERNEL — 4 stable re-benches (39.4/39.6/39.6/39.4 us),
// 7 alternative mechanisms tested and rejected (store widths 128/256-bit,
// batch depths 1/2/4, row-per-CTA / 2-rows / persistent 128KB slabs,
// L2 evict-class partitioning across graph replays, driver memset node +
// sparse scatter). All converge on ~5.1 TB/s in-profile / ~6.6 TB/s
// effective: the HBM3e pure-write ceiling. 256 MB mandatory writes
// (output is poisoned pre-timing) => ~39 us physical floor == measured.
// No SM-side pipe above 20%; nothing left to recruit or elide.
//
// Structure: one 128-thread block per output row (2048 floats = 8 KB).
// Each thread issues 4 batched STG.128 streaming stores (64 B/thread);
// each store round covers a contiguous 2 KB slab -> perfectly coalesced
// full 32B sectors. Index and grad loads are block-uniform L1 broadcast
// hits. Only 1 of 512 (thread, j) slots per row takes the hot branch.

static constexpr unsigned B_DIM = 8;
static constexpr unsigned M_DIM = 4096;
static constexpr unsigned ROWS  = B_DIM * M_DIM;            // 32768 blocks
static constexpr unsigned VEC_PER_ROW = 512;                // 2048 / 4

__global__ void __launch_bounds__(128)
reduce_max_grad_scatter(const float* __restrict__ grad_last,
                        const int* __restrict__ indices,
                        float4* __restrict__ out)
{
    const unsigned row = blockIdx.x;          // b*4096 + i
    const unsigned i   = row & (M_DIM - 1u);
    const unsigned b   = row >> 12;
    const unsigned tid = threadIdx.x;

    // Both loads are block-uniform -> L1 broadcast hits.
    const unsigned ind = (unsigned)__ldg(&indices[i]);
    const float    g   = __ldg(&grad_last[b * M_DIM + i]);

    const unsigned target = ind >> 2;         // which float4 holds the hot lane
    const unsigned lane   = ind & 3u;

    float4* o = out + (size_t)row * VEC_PER_ROW + tid;

#pragma unroll
    for (int j = 0; j < 4; j++) {
        const unsigned q = j * 128u + tid;
        float4 v = make_float4(0.f, 0.f, 0.f, 0.f);
        if (q == target) {                    // taken by exactly 1 of 512 (thread,j)
            v.x = (lane == 0u) ? g : 0.f;
            v.y = (lane == 1u) ? g : 0.f;
            v.z = (lane == 2u) ? g : 0.f;
            v.w = (lane == 3u) ? g : 0.f;
        }
        __stcs(&o[j * 128], v);               // streaming store, evict-first
    }
}

extern "C" void kernel_launch(void* const* d_in, const int* in_sizes, int n_in,
                              void* d_out, int out_size)
{
    const float* grad    = (const float*)d_in[0];
    const int*   indices = (const int*)d_in[1];
    float4*      out     = (float4*)d_out;

    (void)in_sizes; (void)n_in; (void)out_size;

    reduce_max_grad_scatter<<<ROWS, 128>>>(grad, indices, out);
}